// round 15
// baseline (speedup 1.0000x reference)
#include <cuda_runtime.h>
#include <cuda_bf16.h>
#include <cuda_fp16.h>
#include <mma.h>
#include <math.h>
#include <stdint.h>

using namespace nvcuda;

#define NN 100000
#define EE 1600000
#define IN_FEAT 512
#define HID 128
#define NC 7

#define BK 64
#define KPAD 72   // bf16 elems per smem row (144B, 16B-multiple)
#define TM 64     // CTA tile M

#define SCAN_B 512

// -------- scratch (device globals; allocation-free rule) --------
__device__ __align__(256) float g_dinv[NN];
__device__ __align__(256) signed char g_h1i[(size_t)(NN + 128) * HID];  // int8 h1
__device__ __align__(256) float g_h1s[NN + 128];                        // per-row scale
__device__ __align__(256) __half g_h2h[(size_t)NN * 8];                 // fp16 h2
__device__ __align__(256) __nv_bfloat16 g_WT[HID * IN_FEAT];            // W1^T bf16
// CSR by destination
__device__ __align__(256) int    g_cnt[NN];
__device__ __align__(256) int    g_rowptr[NN + 1];
__device__ __align__(256) int    g_bsum[256];
__device__ __align__(256) float2 g_edge[EE];       // .x = src (bit-cast int), .y = norm

// ---------------- degree ----------------
__global__ void k_deg_init(int n) {
    int i = blockIdx.x * blockDim.x + threadIdx.x;
    if (i < n) { g_dinv[i] = 1.0f; g_cnt[i] = 0; }
}
__global__ void k_deg_acc(const int* __restrict__ ei, const float* __restrict__ ew, int E) {
    int e = blockIdx.x * blockDim.x + threadIdx.x;
    if (e < E) {
        int d = ei[E + e];
        atomicAdd(&g_dinv[d], ew[e]);
        atomicAdd(&g_cnt[d], 1);
    }
}

// ---------------- device-wide exclusive scan (3 kernels); dinv fused in scan1 ----------------
__global__ void __launch_bounds__(SCAN_B) k_scan1(int n) {
    __shared__ int sh[SCAN_B];
    const int t = threadIdx.x;
    const int i = blockIdx.x * SCAN_B + t;
    int v = 0;
    if (i < n) {
        v = g_cnt[i];
        float dv = g_dinv[i];                 // fused dinv
        g_dinv[i] = dv > 0.0f ? rsqrtf(dv) : 0.0f;
    }
    sh[t] = v;
    __syncthreads();
#pragma unroll
    for (int off = 1; off < SCAN_B; off <<= 1) {
        int u = (t >= off) ? sh[t - off] : 0;
        __syncthreads();
        sh[t] += u;
        __syncthreads();
    }
    if (i < n) g_rowptr[i] = sh[t] - v;
    if (t == SCAN_B - 1) g_bsum[blockIdx.x] = sh[t];
}

__global__ void __launch_bounds__(256) k_scan2(int nb, int n) {
    __shared__ int sh[256];
    const int t = threadIdx.x;
    int v = (t < nb) ? g_bsum[t] : 0;
    sh[t] = v;
    __syncthreads();
#pragma unroll
    for (int off = 1; off < 256; off <<= 1) {
        int u = (t >= off) ? sh[t - off] : 0;
        __syncthreads();
        sh[t] += u;
        __syncthreads();
    }
    if (t < nb) g_bsum[t] = sh[t] - v;
    if (t == 255) g_rowptr[n] = sh[255];
}

__global__ void __launch_bounds__(SCAN_B) k_scan3(int n) {
    const int i = blockIdx.x * SCAN_B + threadIdx.x;
    if (i < n) {
        int r = g_rowptr[i] + g_bsum[blockIdx.x];
        g_rowptr[i] = r;
        g_cnt[i] = r;
    }
}

// ---------------- reorder edges into CSR with precomputed norm ----------------
__global__ void k_reorder(const int* __restrict__ ei, const float* __restrict__ ew, int E) {
    int e = blockIdx.x * blockDim.x + threadIdx.x;
    if (e >= E) return;
    int s = ei[e];
    int d = ei[E + e];
    float norm = g_dinv[s] * ew[e] * g_dinv[d];
    int pos = atomicAdd(&g_cnt[d], 1);
    g_edge[pos] = make_float2(__int_as_float(s), norm);
}

// ---------------- W1 transpose to bf16 ----------------
__global__ void k_wsplit(const float* __restrict__ W1) {
    int idx = blockIdx.x * blockDim.x + threadIdx.x;
    if (idx >= HID * IN_FEAT) return;
    int k = idx & (IN_FEAT - 1);
    int n = idx >> 9;
    g_WT[n * IN_FEAT + k] = __float2bfloat16(W1[k * HID + n]);
}

// ---------------- GEMM1: h1 = x @ W1 via single-pass bf16 WMMA; int8 output ----------------
#define A_TILE_ELEMS (TM * KPAD)            // 4608
#define B_TILE_ELEMS (HID * KPAD)           // 9216
#define BUF_ELEMS (A_TILE_ELEMS + B_TILE_ELEMS)   // 13824
#define G1_SMEM (2 * BUF_ELEMS * 2)         // 55296 B
#define EPI_STRIDE 132                      // fp32 staging stride (floats)
#define G1_T 128

__device__ __forceinline__ uint32_t smem_u32(const void* p) {
    uint32_t a;
    asm("{ .reg .u64 t; cvta.to.shared.u64 t, %1; cvt.u32.u64 %0, t; }" : "=r"(a) : "l"(p));
    return a;
}
__device__ __forceinline__ void cp16(uint32_t dst, const void* src) {
    asm volatile("cp.async.ca.shared.global [%0], [%1], 16;" :: "r"(dst), "l"(src));
}
__device__ __forceinline__ uint32_t pk2h(float a, float b) {
    __half2 h = __floats2half2_rn(a, b);
    return *(uint32_t*)&h;
}

__global__ void __launch_bounds__(G1_T, 3) k_gemm1_wmma(const float* __restrict__ A, int M) {
    extern __shared__ __align__(16) __nv_bfloat16 sm[];
    const int t = threadIdx.x;
    const int wid = t >> 5;
    const int wm = wid & 1;        // rows wm*32
    const int wn = wid >> 1;       // cols wn*64
    const int rowBase = blockIdx.x * TM;
    const uint32_t sb = smem_u32(sm);

    wmma::fragment<wmma::accumulator, 16, 16, 16, float> acc[2][4];
#pragma unroll
    for (int i = 0; i < 2; i++)
#pragma unroll
        for (int j = 0; j < 4; j++) wmma::fill_fragment(acc[i][j], 0.0f);

    float4 avreg[8];

    auto loadA = [&](int c) {
#pragma unroll
        for (int l = 0; l < 8; l++) {
            int idx = t + l * G1_T;
            int r = idx >> 4;
            int g = idx & 15;
            float4 v = make_float4(0.f, 0.f, 0.f, 0.f);
            if (rowBase + r < M)
                v = *(const float4*)(A + (size_t)(rowBase + r) * IN_FEAT + c * BK + g * 4);
            avreg[l] = v;
        }
    };

    auto cpB = [&](int c, int buf) {
        uint32_t bh = sb + (uint32_t)(buf * BUF_ELEMS + A_TILE_ELEMS) * 2;
#pragma unroll
        for (int l = 0; l < 8; l++) {
            int idx = t + l * G1_T;
            int n = idx >> 3;
            int g = idx & 7;
            uint32_t so = (uint32_t)(n * KPAD + g * 8) * 2;
            cp16(bh + so, g_WT + (size_t)n * IN_FEAT + c * BK + g * 8);
        }
        asm volatile("cp.async.commit_group;" ::: "memory");
    };

    auto storeA = [&](int buf) {
        __nv_bfloat16* Ah = sm + (size_t)buf * BUF_ELEMS;
#pragma unroll
        for (int l = 0; l < 8; l++) {
            int idx = t + l * G1_T;
            int r = idx >> 4;
            int g = idx & 15;
            float4 v = avreg[l];
            int off = r * KPAD + g * 4;
            *(__nv_bfloat162*)(Ah + off)     = __nv_bfloat162(__float2bfloat16(v.x), __float2bfloat16(v.y));
            *(__nv_bfloat162*)(Ah + off + 2) = __nv_bfloat162(__float2bfloat16(v.z), __float2bfloat16(v.w));
        }
    };

    auto compute = [&](int buf) {
        const __nv_bfloat16* Ah = sm + (size_t)buf * BUF_ELEMS;
        const __nv_bfloat16* Bh = Ah + A_TILE_ELEMS;
#pragma unroll
        for (int kk = 0; kk < BK; kk += 16) {
            wmma::fragment<wmma::matrix_a, 16, 16, 16, __nv_bfloat16, wmma::row_major> fa[2];
            wmma::fragment<wmma::matrix_b, 16, 16, 16, __nv_bfloat16, wmma::col_major> fb[4];
#pragma unroll
            for (int i = 0; i < 2; i++)
                wmma::load_matrix_sync(fa[i], Ah + (wm * 32 + i * 16) * KPAD + kk, KPAD);
#pragma unroll
            for (int j = 0; j < 4; j++)
                wmma::load_matrix_sync(fb[j], Bh + (wn * 64 + j * 16) * KPAD + kk, KPAD);
#pragma unroll
            for (int i = 0; i < 2; i++)
#pragma unroll
                for (int j = 0; j < 4; j++)
                    wmma::mma_sync(acc[i][j], fa[i], fb[j], acc[i][j]);
        }
    };

    loadA(0);
    cpB(0, 0);
    storeA(0);
    asm volatile("cp.async.wait_group 0;" ::: "memory");
    __syncthreads();

    const int NSTAGE = IN_FEAT / BK;  // 8
    for (int c = 0; c < NSTAGE; c++) {
        const int cur = c & 1;
        const int nxt = 1 - cur;
        if (c + 1 < NSTAGE) {
            loadA(c + 1);
            cpB(c + 1, nxt);
        }
        compute(cur);
        if (c + 1 < NSTAGE) {
            storeA(nxt);
            asm volatile("cp.async.wait_group 0;" ::: "memory");
        }
        __syncthreads();
    }

    // epilogue: stage fp32 accs in smem, per-row int8 quantization, coalesced STG
    {
        float* fs = (float*)sm;
#pragma unroll
        for (int i = 0; i < 2; i++)
#pragma unroll
            for (int j = 0; j < 4; j++)
                wmma::store_matrix_sync(fs + (wm * 32 + i * 16) * EPI_STRIDE + wn * 64 + j * 16,
                                        acc[i][j], EPI_STRIDE, wmma::mem_row_major);
        __syncthreads();
        const int lane = t & 31;
        const unsigned m16 = 0xFFFFu << (lane & 16);   // 16-lane half-warp group (one row)
#pragma unroll
        for (int u = 0; u < 8; u++) {
            int idx = t + u * G1_T;
            int r = idx >> 4;            // threads 16g..16g+15 share row r
            int c = (idx & 15) * 8;
            const float* src = fs + r * EPI_STRIDE + c;
            float v[8];
            float mx = 0.0f;
#pragma unroll
            for (int k = 0; k < 8; k++) { v[k] = src[k]; mx = fmaxf(mx, fabsf(v[k])); }
#pragma unroll
            for (int off = 8; off > 0; off >>= 1)
                mx = fmaxf(mx, __shfl_xor_sync(m16, mx, off));
            float inv = mx > 0.0f ? 127.0f / mx : 0.0f;
            uint32_t lo = 0, hi = 0;
#pragma unroll
            for (int k = 0; k < 4; k++) {
                int q = __float2int_rn(v[k] * inv);
                lo |= ((uint32_t)(q & 0xff)) << (8 * k);
            }
#pragma unroll
            for (int k = 0; k < 4; k++) {
                int q = __float2int_rn(v[k + 4] * inv);
                hi |= ((uint32_t)(q & 0xff)) << (8 * k);
            }
            *(uint2*)(g_h1i + (size_t)(rowBase + r) * HID + c) = make_uint2(lo, hi);
            if ((t & 15) == 0) g_h1s[rowBase + r] = mx * (1.0f / 127.0f);
        }
    }
}

// ---------------- layer1 aggregate (int8 gather) + ELU + @W2 (warp per node) ----------------
__device__ __forceinline__ float4 dq8(uint32_t u, float s) {
    float4 r;
    r.x = (float)((int)(signed char)(u))       * s;
    r.y = (float)((int)(signed char)(u >> 8))  * s;
    r.z = (float)((int)(signed char)(u >> 16)) * s;
    r.w = (float)((int)(signed char)(u >> 24)) * s;
    return r;
}

__global__ void __launch_bounds__(256) k_agg1_fused(const float* __restrict__ b1,
                                                    const float* __restrict__ W2, int n) {
    int node = (int)(((size_t)blockIdx.x * blockDim.x + threadIdx.x) >> 5);
    int lane = threadIdx.x & 31;
    if (node >= n) return;

    const int beg = g_rowptr[node];
    const int end = g_rowptr[node + 1];
    float d = g_dinv[node];
    float dd = d * d;

    // self-loop init (int8 h1, dequant scale folded with dinv^2)
    float4 acc;
    {
        uint32_t u = *(const uint32_t*)(g_h1i + (size_t)node * HID + lane * 4);
        acc = dq8(u, dd * g_h1s[node]);
    }

    int e = beg;
    for (; e + 4 <= end; e += 4) {
        float2 e0 = g_edge[e];
        float2 e1 = g_edge[e + 1];
        float2 e2 = g_edge[e + 2];
        float2 e3 = g_edge[e + 3];
        int s0 = __float_as_int(e0.x), s1 = __float_as_int(e1.x);
        int s2 = __float_as_int(e2.x), s3 = __float_as_int(e3.x);
        float c0 = e0.y * g_h1s[s0];
        float c1 = e1.y * g_h1s[s1];
        float c2 = e2.y * g_h1s[s2];
        float c3 = e3.y * g_h1s[s3];
        uint32_t u0 = *(const uint32_t*)(g_h1i + (size_t)s0 * HID + lane * 4);
        uint32_t u1 = *(const uint32_t*)(g_h1i + (size_t)s1 * HID + lane * 4);
        uint32_t u2 = *(const uint32_t*)(g_h1i + (size_t)s2 * HID + lane * 4);
        uint32_t u3 = *(const uint32_t*)(g_h1i + (size_t)s3 * HID + lane * 4);
        float4 v0 = dq8(u0, c0), v1 = dq8(u1, c1), v2 = dq8(u2, c2), v3 = dq8(u3, c3);
        acc.x += v0.x + v1.x + v2.x + v3.x;
        acc.y += v0.y + v1.y + v2.y + v3.y;
        acc.z += v0.z + v1.z + v2.z + v3.z;
        acc.w += v0.w + v1.w + v2.w + v3.w;
    }
    for (; e < end; e++) {
        float2 ed = g_edge[e];
        int s = __float_as_int(ed.x);
        uint32_t u = *(const uint32_t*)(g_h1i + (size_t)s * HID + lane * 4);
        float4 v = dq8(u, ed.y * g_h1s[s]);
        acc.x += v.x; acc.y += v.y; acc.z += v.z; acc.w += v.w;
    }

    float sv[NC];
#pragma unroll
    for (int c = 0; c < NC; c++) sv[c] = 0.0f;
    float av[4] = {acc.x, acc.y, acc.z, acc.w};
#pragma unroll
    for (int j = 0; j < 4; j++) {
        int f = lane * 4 + j;
        float v = av[j] + b1[f];
        float a = v > 0.0f ? v : expm1f(v);
#pragma unroll
        for (int c = 0; c < NC; c++) sv[c] = fmaf(a, W2[f * NC + c], sv[c]);
    }
#pragma unroll
    for (int off = 16; off > 0; off >>= 1)
#pragma unroll
        for (int c = 0; c < NC; c++) sv[c] += __shfl_down_sync(0xffffffffu, sv[c], off);
    if (lane == 0) {
        uint4 o;
        o.x = pk2h(sv[0], sv[1]);
        o.y = pk2h(sv[2], sv[3]);
        o.z = pk2h(sv[4], sv[5]);
        o.w = pk2h(sv[6], 0.0f);
        *(uint4*)(g_h2h + (size_t)node * 8) = o;
    }
}

// ---------------- layer2 aggregate (fp16 h2) + bias + log_softmax (8 lanes per node) ----------------
__global__ void __launch_bounds__(256) k_agg2_fused(const float* __restrict__ b2,
                                                    float* __restrict__ out, int n) {
    int node = (int)(((size_t)blockIdx.x * blockDim.x + threadIdx.x) >> 3);
    int l8 = threadIdx.x & 7;
    if (node >= n) return;
    const unsigned gmask = 0xFFu << (threadIdx.x & 24);

    const int beg = g_rowptr[node];
    const int end = g_rowptr[node + 1];
    float d = g_dinv[node];
    float acc = __half2float(g_h2h[(size_t)node * 8 + l8]) * d * d;

    int e = beg;
    for (; e + 4 <= end; e += 4) {
        float2 e0 = g_edge[e];
        float2 e1 = g_edge[e + 1];
        float2 e2 = g_edge[e + 2];
        float2 e3 = g_edge[e + 3];
        float v0 = __half2float(g_h2h[(size_t)__float_as_int(e0.x) * 8 + l8]);
        float v1 = __half2float(g_h2h[(size_t)__float_as_int(e1.x) * 8 + l8]);
        float v2 = __half2float(g_h2h[(size_t)__float_as_int(e2.x) * 8 + l8]);
        float v3 = __half2float(g_h2h[(size_t)__float_as_int(e3.x) * 8 + l8]);
        acc = fmaf(v0, e0.y, acc);
        acc = fmaf(v1, e1.y, acc);
        acc = fmaf(v2, e2.y, acc);
        acc = fmaf(v3, e3.y, acc);
    }
    for (; e < end; e++) {
        float2 ed = g_edge[e];
        acc = fmaf(__half2float(g_h2h[(size_t)__float_as_int(ed.x) * 8 + l8]), ed.y, acc);
    }

    float z = (l8 < NC) ? acc + b2[l8] : -1e30f;
    float m = z;
#pragma unroll
    for (int off = 4; off > 0; off >>= 1)
        m = fmaxf(m, __shfl_xor_sync(gmask, m, off));
    float ex = (l8 < NC) ? expf(z - m) : 0.0f;
    float sum = ex;
#pragma unroll
    for (int off = 4; off > 0; off >>= 1)
        sum += __shfl_xor_sync(gmask, sum, off);
    float lse = m + logf(sum);
    if (l8 < NC) out[(size_t)node * NC + l8] = z - lse;
}

// ---------------- launcher ----------------
extern "C" void kernel_launch(void* const* d_in, const int* in_sizes, int n_in,
                              void* d_out, int out_size) {
    const float* x  = (const float*)d_in[0];
    const int*   ei = (const int*)d_in[1];
    const float* ew = (const float*)d_in[2];
    const float* W1 = (const float*)d_in[3];
    const float* b1 = (const float*)d_in[4];
    const float* W2 = (const float*)d_in[5];
    const float* b2 = (const float*)d_in[6];
    float* out = (float*)d_out;

    const int Nn = in_sizes[0] / IN_FEAT;   // 100000
    const int E  = in_sizes[2];             // 1600000
    const int nb = (Nn + SCAN_B - 1) / SCAN_B;

    static cudaStream_t s1 = 0;
    static cudaEvent_t ev_fork = 0, ev_join = 0;
    static int init_done = 0;
    if (!init_done) {
        cudaFuncSetAttribute(k_gemm1_wmma, cudaFuncAttributeMaxDynamicSharedMemorySize, G1_SMEM);
        cudaStreamCreateWithFlags(&s1, cudaStreamNonBlocking);
        cudaEventCreateWithFlags(&ev_fork, cudaEventDisableTiming);
        cudaEventCreateWithFlags(&ev_join, cudaEventDisableTiming);
        init_done = 1;
    }

    // fork: edge/CSR chain on s1, GEMM chain on the origin stream
    cudaEventRecord(ev_fork, 0);
    cudaStreamWaitEvent(s1, ev_fork, 0);

    k_wsplit<<<(HID * IN_FEAT + 255) / 256, 256>>>(W1);
    k_deg_init<<<(Nn + 255) / 256, 256, 0, s1>>>(Nn);
    k_deg_acc<<<(E + 255) / 256, 256, 0, s1>>>(ei, ew, E);

    k_gemm1_wmma<<<(Nn + TM - 1) / TM, G1_T, G1_SMEM>>>(x, Nn);   // 4th launch (ncu slot)

    k_scan1<<<nb, SCAN_B, 0, s1>>>(Nn);   // dinv fused
    k_scan2<<<1, 256, 0, s1>>>(nb, Nn);
    k_scan3<<<nb, SCAN_B, 0, s1>>>(Nn);
    k_reorder<<<(E + 255) / 256, 256, 0, s1>>>(ei, ew, E);

    // join: aggregation needs both GEMM output and CSR
    cudaEventRecord(ev_join, s1);
    cudaStreamWaitEvent(0, ev_join, 0);

    k_agg1_fused<<<(Nn + 7) / 8, 256>>>(b1, W2, Nn);    // warp per node
    k_agg2_fused<<<(Nn + 31) / 32, 256>>>(b2, out, Nn); // 8 lanes per node
}

// round 16
// speedup vs baseline: 1.0021x; 1.0021x over previous
#include <cuda_runtime.h>
#include <cuda_bf16.h>
#include <cuda_fp16.h>
#include <mma.h>
#include <math.h>
#include <stdint.h>

using namespace nvcuda;

#define NN 100000
#define EE 1600000
#define IN_FEAT 512
#define HID 128
#define NC 7

#define BK 64
#define KPAD 72   // bf16 elems per smem row (144B, 16B-multiple)
#define TM 64     // CTA tile M

#define SCAN_B 512

// -------- scratch (device globals; allocation-free rule) --------
__device__ __align__(256) float g_dinv[NN];
__device__ __align__(256) __half g_h1h[(size_t)(NN + 128) * HID];  // fp16 h1 (pad for tail CTA)
__device__ __align__(256) __half g_h2h[(size_t)NN * 8];            // fp16 h2
__device__ __align__(256) __nv_bfloat16 g_WT[HID * IN_FEAT];       // W1^T bf16
// CSR by destination
__device__ __align__(256) int    g_cnt[NN];
__device__ __align__(256) int    g_rowptr[NN + 1];
__device__ __align__(256) int    g_bsum[256];
__device__ __align__(256) float2 g_edge[EE];       // .x = src (bit-cast int), .y = norm

// ---------------- degree ----------------
__global__ void k_deg_init(int n) {
    int i = blockIdx.x * blockDim.x + threadIdx.x;
    if (i < n) { g_dinv[i] = 1.0f; g_cnt[i] = 0; }
}
__global__ void k_deg_acc(const int* __restrict__ ei, const float* __restrict__ ew, int E) {
    int e = blockIdx.x * blockDim.x + threadIdx.x;
    if (e < E) {
        int d = ei[E + e];
        atomicAdd(&g_dinv[d], ew[e]);
        atomicAdd(&g_cnt[d], 1);
    }
}

// ---------------- device-wide exclusive scan (3 kernels); dinv fused in scan1 ----------------
__global__ void __launch_bounds__(SCAN_B) k_scan1(int n) {
    __shared__ int sh[SCAN_B];
    const int t = threadIdx.x;
    const int i = blockIdx.x * SCAN_B + t;
    int v = 0;
    if (i < n) {
        v = g_cnt[i];
        float dv = g_dinv[i];                 // fused dinv
        g_dinv[i] = dv > 0.0f ? rsqrtf(dv) : 0.0f;
    }
    sh[t] = v;
    __syncthreads();
#pragma unroll
    for (int off = 1; off < SCAN_B; off <<= 1) {
        int u = (t >= off) ? sh[t - off] : 0;
        __syncthreads();
        sh[t] += u;
        __syncthreads();
    }
    if (i < n) g_rowptr[i] = sh[t] - v;
    if (t == SCAN_B - 1) g_bsum[blockIdx.x] = sh[t];
}

__global__ void __launch_bounds__(256) k_scan2(int nb, int n) {
    __shared__ int sh[256];
    const int t = threadIdx.x;
    int v = (t < nb) ? g_bsum[t] : 0;
    sh[t] = v;
    __syncthreads();
#pragma unroll
    for (int off = 1; off < 256; off <<= 1) {
        int u = (t >= off) ? sh[t - off] : 0;
        __syncthreads();
        sh[t] += u;
        __syncthreads();
    }
    if (t < nb) g_bsum[t] = sh[t] - v;
    if (t == 255) g_rowptr[n] = sh[255];
}

__global__ void __launch_bounds__(SCAN_B) k_scan3(int n) {
    const int i = blockIdx.x * SCAN_B + threadIdx.x;
    if (i < n) {
        int r = g_rowptr[i] + g_bsum[blockIdx.x];
        g_rowptr[i] = r;
        g_cnt[i] = r;
    }
}

// ---------------- reorder edges into CSR with precomputed norm ----------------
__global__ void k_reorder(const int* __restrict__ ei, const float* __restrict__ ew, int E) {
    int e = blockIdx.x * blockDim.x + threadIdx.x;
    if (e >= E) return;
    int s = ei[e];
    int d = ei[E + e];
    float norm = g_dinv[s] * ew[e] * g_dinv[d];
    int pos = atomicAdd(&g_cnt[d], 1);
    g_edge[pos] = make_float2(__int_as_float(s), norm);
}

// ---------------- W1 transpose to bf16 ----------------
__global__ void k_wsplit(const float* __restrict__ W1) {
    int idx = blockIdx.x * blockDim.x + threadIdx.x;
    if (idx >= HID * IN_FEAT) return;
    int k = idx & (IN_FEAT - 1);
    int n = idx >> 9;
    g_WT[n * IN_FEAT + k] = __float2bfloat16(W1[k * HID + n]);
}

// ---------------- GEMM1: h1 = x @ W1 via single-pass bf16 WMMA ----------------
#define A_TILE_ELEMS (TM * KPAD)            // 4608
#define B_TILE_ELEMS (HID * KPAD)           // 9216
#define BUF_ELEMS (A_TILE_ELEMS + B_TILE_ELEMS)   // 13824
#define G1_SMEM (2 * BUF_ELEMS * 2)         // 55296 B
#define EPI_STRIDE 132                      // fp32 staging stride (floats)
#define G1_T 128

__device__ __forceinline__ uint32_t smem_u32(const void* p) {
    uint32_t a;
    asm("{ .reg .u64 t; cvta.to.shared.u64 t, %1; cvt.u32.u64 %0, t; }" : "=r"(a) : "l"(p));
    return a;
}
__device__ __forceinline__ void cp16(uint32_t dst, const void* src) {
    asm volatile("cp.async.ca.shared.global [%0], [%1], 16;" :: "r"(dst), "l"(src));
}
__device__ __forceinline__ uint32_t pk2h(float a, float b) {
    __half2 h = __floats2half2_rn(a, b);
    return *(uint32_t*)&h;
}

__global__ void __launch_bounds__(G1_T, 3) k_gemm1_wmma(const float* __restrict__ A, int M) {
    extern __shared__ __align__(16) __nv_bfloat16 sm[];
    const int t = threadIdx.x;
    const int wid = t >> 5;
    const int wm = wid & 1;        // rows wm*32
    const int wn = wid >> 1;       // cols wn*64
    const int rowBase = blockIdx.x * TM;
    const uint32_t sb = smem_u32(sm);

    wmma::fragment<wmma::accumulator, 16, 16, 16, float> acc[2][4];
#pragma unroll
    for (int i = 0; i < 2; i++)
#pragma unroll
        for (int j = 0; j < 4; j++) wmma::fill_fragment(acc[i][j], 0.0f);

    float4 avreg[8];

    auto loadA = [&](int c) {
#pragma unroll
        for (int l = 0; l < 8; l++) {
            int idx = t + l * G1_T;
            int r = idx >> 4;
            int g = idx & 15;
            float4 v = make_float4(0.f, 0.f, 0.f, 0.f);
            if (rowBase + r < M)
                v = *(const float4*)(A + (size_t)(rowBase + r) * IN_FEAT + c * BK + g * 4);
            avreg[l] = v;
        }
    };

    auto cpB = [&](int c, int buf) {
        uint32_t bh = sb + (uint32_t)(buf * BUF_ELEMS + A_TILE_ELEMS) * 2;
#pragma unroll
        for (int l = 0; l < 8; l++) {
            int idx = t + l * G1_T;
            int n = idx >> 3;
            int g = idx & 7;
            uint32_t so = (uint32_t)(n * KPAD + g * 8) * 2;
            cp16(bh + so, g_WT + (size_t)n * IN_FEAT + c * BK + g * 8);
        }
        asm volatile("cp.async.commit_group;" ::: "memory");
    };

    auto storeA = [&](int buf) {
        __nv_bfloat16* Ah = sm + (size_t)buf * BUF_ELEMS;
#pragma unroll
        for (int l = 0; l < 8; l++) {
            int idx = t + l * G1_T;
            int r = idx >> 4;
            int g = idx & 15;
            float4 v = avreg[l];
            int off = r * KPAD + g * 4;
            *(__nv_bfloat162*)(Ah + off)     = __nv_bfloat162(__float2bfloat16(v.x), __float2bfloat16(v.y));
            *(__nv_bfloat162*)(Ah + off + 2) = __nv_bfloat162(__float2bfloat16(v.z), __float2bfloat16(v.w));
        }
    };

    auto compute = [&](int buf) {
        const __nv_bfloat16* Ah = sm + (size_t)buf * BUF_ELEMS;
        const __nv_bfloat16* Bh = Ah + A_TILE_ELEMS;
#pragma unroll
        for (int kk = 0; kk < BK; kk += 16) {
            wmma::fragment<wmma::matrix_a, 16, 16, 16, __nv_bfloat16, wmma::row_major> fa[2];
            wmma::fragment<wmma::matrix_b, 16, 16, 16, __nv_bfloat16, wmma::col_major> fb[4];
#pragma unroll
            for (int i = 0; i < 2; i++)
                wmma::load_matrix_sync(fa[i], Ah + (wm * 32 + i * 16) * KPAD + kk, KPAD);
#pragma unroll
            for (int j = 0; j < 4; j++)
                wmma::load_matrix_sync(fb[j], Bh + (wn * 64 + j * 16) * KPAD + kk, KPAD);
#pragma unroll
            for (int i = 0; i < 2; i++)
#pragma unroll
                for (int j = 0; j < 4; j++)
                    wmma::mma_sync(acc[i][j], fa[i], fb[j], acc[i][j]);
        }
    };

    loadA(0);
    cpB(0, 0);
    storeA(0);
    asm volatile("cp.async.wait_group 0;" ::: "memory");
    __syncthreads();

    const int NSTAGE = IN_FEAT / BK;  // 8
    for (int c = 0; c < NSTAGE; c++) {
        const int cur = c & 1;
        const int nxt = 1 - cur;
        if (c + 1 < NSTAGE) {
            loadA(c + 1);
            cpB(c + 1, nxt);
        }
        compute(cur);
        if (c + 1 < NSTAGE) {
            storeA(nxt);
            asm volatile("cp.async.wait_group 0;" ::: "memory");
        }
        __syncthreads();
    }

    // epilogue: stage fp32 accs in smem, convert to fp16, coalesced STG
    {
        float* fs = (float*)sm;
#pragma unroll
        for (int i = 0; i < 2; i++)
#pragma unroll
            for (int j = 0; j < 4; j++)
                wmma::store_matrix_sync(fs + (wm * 32 + i * 16) * EPI_STRIDE + wn * 64 + j * 16,
                                        acc[i][j], EPI_STRIDE, wmma::mem_row_major);
        __syncthreads();
#pragma unroll
        for (int u = 0; u < 8; u++) {
            int idx = t + u * G1_T;
            int r = idx >> 4;
            int c = (idx & 15) * 8;
            const float* src = fs + r * EPI_STRIDE + c;
            uint4 o;
            o.x = pk2h(src[0], src[1]);
            o.y = pk2h(src[2], src[3]);
            o.z = pk2h(src[4], src[5]);
            o.w = pk2h(src[6], src[7]);
            *(uint4*)(g_h1h + (size_t)(rowBase + r) * HID + c) = o;
        }
    }
}

// ---------------- layer1 aggregate (half2 FMA) + ELU + @W2 (warp per node) ----------------
__global__ void __launch_bounds__(256) k_agg1_fused(const float* __restrict__ b1,
                                                    const float* __restrict__ W2, int n) {
    int node = (int)(((size_t)blockIdx.x * blockDim.x + threadIdx.x) >> 5);
    int lane = threadIdx.x & 31;
    if (node >= n) return;

    const int beg = g_rowptr[node];
    const int end = g_rowptr[node + 1];
    float d = g_dinv[node];
    float dd = d * d;

    // self-loop init in half2
    uint2 su = *((const uint2*)(g_h1h + (size_t)node * HID) + lane);
    __half2 dd2 = __float2half2_rn(dd);
    __half2 acc0 = __hmul2(*(__half2*)&su.x, dd2);
    __half2 acc1 = __hmul2(*(__half2*)&su.y, dd2);

    int e = beg;
    for (; e + 4 <= end; e += 4) {
        float2 e0 = g_edge[e];
        float2 e1 = g_edge[e + 1];
        float2 e2 = g_edge[e + 2];
        float2 e3 = g_edge[e + 3];
        __half2 n0 = __float2half2_rn(e0.y);
        __half2 n1 = __float2half2_rn(e1.y);
        __half2 n2 = __float2half2_rn(e2.y);
        __half2 n3 = __float2half2_rn(e3.y);
        uint2 u0 = *((const uint2*)(g_h1h + (size_t)__float_as_int(e0.x) * HID) + lane);
        uint2 u1 = *((const uint2*)(g_h1h + (size_t)__float_as_int(e1.x) * HID) + lane);
        uint2 u2 = *((const uint2*)(g_h1h + (size_t)__float_as_int(e2.x) * HID) + lane);
        uint2 u3 = *((const uint2*)(g_h1h + (size_t)__float_as_int(e3.x) * HID) + lane);
        acc0 = __hfma2(*(__half2*)&u0.x, n0, acc0);
        acc1 = __hfma2(*(__half2*)&u0.y, n0, acc1);
        acc0 = __hfma2(*(__half2*)&u1.x, n1, acc0);
        acc1 = __hfma2(*(__half2*)&u1.y, n1, acc1);
        acc0 = __hfma2(*(__half2*)&u2.x, n2, acc0);
        acc1 = __hfma2(*(__half2*)&u2.y, n2, acc1);
        acc0 = __hfma2(*(__half2*)&u3.x, n3, acc0);
        acc1 = __hfma2(*(__half2*)&u3.y, n3, acc1);
    }
    for (; e < end; e++) {
        float2 ed = g_edge[e];
        __half2 nm = __float2half2_rn(ed.y);
        uint2 u = *((const uint2*)(g_h1h + (size_t)__float_as_int(ed.x) * HID) + lane);
        acc0 = __hfma2(*(__half2*)&u.x, nm, acc0);
        acc1 = __hfma2(*(__half2*)&u.y, nm, acc1);
    }

    float2 f0 = __half22float2(acc0);
    float2 f1 = __half22float2(acc1);
    float av[4] = {f0.x, f0.y, f1.x, f1.y};

    float sv[NC];
#pragma unroll
    for (int c = 0; c < NC; c++) sv[c] = 0.0f;
#pragma unroll
    for (int j = 0; j < 4; j++) {
        int f = lane * 4 + j;
        float v = av[j] + b1[f];
        float a = v > 0.0f ? v : (__expf(v) - 1.0f);
#pragma unroll
        for (int c = 0; c < NC; c++) sv[c] = fmaf(a, W2[f * NC + c], sv[c]);
    }
#pragma unroll
    for (int off = 16; off > 0; off >>= 1)
#pragma unroll
        for (int c = 0; c < NC; c++) sv[c] += __shfl_down_sync(0xffffffffu, sv[c], off);
    if (lane == 0) {
        uint4 o;
        o.x = pk2h(sv[0], sv[1]);
        o.y = pk2h(sv[2], sv[3]);
        o.z = pk2h(sv[4], sv[5]);
        o.w = pk2h(sv[6], 0.0f);
        *(uint4*)(g_h2h + (size_t)node * 8) = o;
    }
}

// ---------------- layer2 aggregate (fp16 h2) + bias + log_softmax (8 lanes per node) ----------------
__global__ void __launch_bounds__(256) k_agg2_fused(const float* __restrict__ b2,
                                                    float* __restrict__ out, int n) {
    int node = (int)(((size_t)blockIdx.x * blockDim.x + threadIdx.x) >> 3);
    int l8 = threadIdx.x & 7;
    if (node >= n) return;
    const unsigned gmask = 0xFFu << (threadIdx.x & 24);

    const int beg = g_rowptr[node];
    const int end = g_rowptr[node + 1];
    float d = g_dinv[node];
    float acc = __half2float(g_h2h[(size_t)node * 8 + l8]) * d * d;

    int e = beg;
    for (; e + 4 <= end; e += 4) {
        float2 e0 = g_edge[e];
        float2 e1 = g_edge[e + 1];
        float2 e2 = g_edge[e + 2];
        float2 e3 = g_edge[e + 3];
        float v0 = __half2float(g_h2h[(size_t)__float_as_int(e0.x) * 8 + l8]);
        float v1 = __half2float(g_h2h[(size_t)__float_as_int(e1.x) * 8 + l8]);
        float v2 = __half2float(g_h2h[(size_t)__float_as_int(e2.x) * 8 + l8]);
        float v3 = __half2float(g_h2h[(size_t)__float_as_int(e3.x) * 8 + l8]);
        acc = fmaf(v0, e0.y, acc);
        acc = fmaf(v1, e1.y, acc);
        acc = fmaf(v2, e2.y, acc);
        acc = fmaf(v3, e3.y, acc);
    }
    for (; e < end; e++) {
        float2 ed = g_edge[e];
        acc = fmaf(__half2float(g_h2h[(size_t)__float_as_int(ed.x) * 8 + l8]), ed.y, acc);
    }

    float z = (l8 < NC) ? acc + b2[l8] : -1e30f;
    float m = z;
#pragma unroll
    for (int off = 4; off > 0; off >>= 1)
        m = fmaxf(m, __shfl_xor_sync(gmask, m, off));
    float ex = (l8 < NC) ? expf(z - m) : 0.0f;
    float sum = ex;
#pragma unroll
    for (int off = 4; off > 0; off >>= 1)
        sum += __shfl_xor_sync(gmask, sum, off);
    float lse = m + logf(sum);
    if (l8 < NC) out[(size_t)node * NC + l8] = z - lse;
}

// ---------------- launcher ----------------
extern "C" void kernel_launch(void* const* d_in, const int* in_sizes, int n_in,
                              void* d_out, int out_size) {
    const float* x  = (const float*)d_in[0];
    const int*   ei = (const int*)d_in[1];
    const float* ew = (const float*)d_in[2];
    const float* W1 = (const float*)d_in[3];
    const float* b1 = (const float*)d_in[4];
    const float* W2 = (const float*)d_in[5];
    const float* b2 = (const float*)d_in[6];
    float* out = (float*)d_out;

    const int Nn = in_sizes[0] / IN_FEAT;   // 100000
    const int E  = in_sizes[2];             // 1600000
    const int nb = (Nn + SCAN_B - 1) / SCAN_B;

    static cudaStream_t s1 = 0;
    static cudaEvent_t ev_fork = 0, ev_join = 0;
    static int init_done = 0;
    if (!init_done) {
        cudaFuncSetAttribute(k_gemm1_wmma, cudaFuncAttributeMaxDynamicSharedMemorySize, G1_SMEM);
        cudaStreamCreateWithFlags(&s1, cudaStreamNonBlocking);
        cudaEventCreateWithFlags(&ev_fork, cudaEventDisableTiming);
        cudaEventCreateWithFlags(&ev_join, cudaEventDisableTiming);
        init_done = 1;
    }

    // fork: edge/CSR chain on s1, GEMM chain on the origin stream
    cudaEventRecord(ev_fork, 0);
    cudaStreamWaitEvent(s1, ev_fork, 0);

    k_wsplit<<<(HID * IN_FEAT + 255) / 256, 256>>>(W1);
    k_deg_init<<<(Nn + 255) / 256, 256, 0, s1>>>(Nn);
    k_deg_acc<<<(E + 255) / 256, 256, 0, s1>>>(ei, ew, E);

    k_gemm1_wmma<<<(Nn + TM - 1) / TM, G1_T, G1_SMEM>>>(x, Nn);   // 4th launch (ncu slot)

    k_scan1<<<nb, SCAN_B, 0, s1>>>(Nn);   // dinv fused
    k_scan2<<<1, 256, 0, s1>>>(nb, Nn);
    k_scan3<<<nb, SCAN_B, 0, s1>>>(Nn);
    k_reorder<<<(E + 255) / 256, 256, 0, s1>>>(ei, ew, E);

    // join: aggregation needs both GEMM output and CSR
    cudaEventRecord(ev_join, s1);
    cudaStreamWaitEvent(0, ev_join, 0);

    k_agg1_fused<<<(Nn + 7) / 8, 256>>>(b1, W2, Nn);    // warp per node
    k_agg2_fused<<<(Nn + 31) / 32, 256>>>(b2, out, Nn); // 8 lanes per node
}

// round 17
// speedup vs baseline: 1.1536x; 1.1511x over previous
#include <cuda_runtime.h>
#include <cuda_bf16.h>
#include <cuda_fp16.h>
#include <mma.h>
#include <math.h>
#include <stdint.h>

using namespace nvcuda;

#define NN 100000
#define EE 1600000
#define IN_FEAT 512
#define HID 128
#define NC 7

#define BK 64
#define KPAD 72   // bf16 elems per smem row (144B, 16B-multiple)
#define TM 64     // CTA tile M

#define SCAN_B 512

// -------- scratch (device globals; allocation-free rule) --------
__device__ __align__(256) float g_dinv[NN];
__device__ __align__(256) __half g_h1h[(size_t)(NN + 128) * HID];  // fp16 h1 (pad for tail CTA)
__device__ __align__(256) __half g_h2h[(size_t)NN * 8];            // fp16 h2
__device__ __align__(256) __nv_bfloat16 g_WT[HID * IN_FEAT];       // W1^T bf16
// CSR by destination
__device__ __align__(256) int    g_cnt[NN];
__device__ __align__(256) int    g_rowptr[NN + 1];
__device__ __align__(256) int    g_bsum[256];
__device__ __align__(256) float2 g_edge[EE];       // .x = src (bit-cast int), .y = norm

// ---------------- degree ----------------
__global__ void k_deg_init(int n) {
    int i = blockIdx.x * blockDim.x + threadIdx.x;
    if (i < n) { g_dinv[i] = 1.0f; g_cnt[i] = 0; }
}
__global__ void k_deg_acc(const int* __restrict__ ei, const float* __restrict__ ew, int E) {
    int e = blockIdx.x * blockDim.x + threadIdx.x;
    if (e < E) {
        int d = ei[E + e];
        atomicAdd(&g_dinv[d], ew[e]);
        atomicAdd(&g_cnt[d], 1);
    }
}

// ---------------- device-wide exclusive scan (3 kernels); dinv fused in scan1 ----------------
__global__ void __launch_bounds__(SCAN_B) k_scan1(int n) {
    __shared__ int sh[SCAN_B];
    const int t = threadIdx.x;
    const int i = blockIdx.x * SCAN_B + t;
    int v = 0;
    if (i < n) {
        v = g_cnt[i];
        float dv = g_dinv[i];                 // fused dinv
        g_dinv[i] = dv > 0.0f ? rsqrtf(dv) : 0.0f;
    }
    sh[t] = v;
    __syncthreads();
#pragma unroll
    for (int off = 1; off < SCAN_B; off <<= 1) {
        int u = (t >= off) ? sh[t - off] : 0;
        __syncthreads();
        sh[t] += u;
        __syncthreads();
    }
    if (i < n) g_rowptr[i] = sh[t] - v;
    if (t == SCAN_B - 1) g_bsum[blockIdx.x] = sh[t];
}

__global__ void __launch_bounds__(256) k_scan2(int nb, int n) {
    __shared__ int sh[256];
    const int t = threadIdx.x;
    int v = (t < nb) ? g_bsum[t] : 0;
    sh[t] = v;
    __syncthreads();
#pragma unroll
    for (int off = 1; off < 256; off <<= 1) {
        int u = (t >= off) ? sh[t - off] : 0;
        __syncthreads();
        sh[t] += u;
        __syncthreads();
    }
    if (t < nb) g_bsum[t] = sh[t] - v;
    if (t == 255) g_rowptr[n] = sh[255];
}

__global__ void __launch_bounds__(SCAN_B) k_scan3(int n) {
    const int i = blockIdx.x * SCAN_B + threadIdx.x;
    if (i < n) {
        int r = g_rowptr[i] + g_bsum[blockIdx.x];
        g_rowptr[i] = r;
        g_cnt[i] = r;
    }
}

// ---------------- reorder edges into CSR with precomputed norm ----------------
__global__ void k_reorder(const int* __restrict__ ei, const float* __restrict__ ew, int E) {
    int e = blockIdx.x * blockDim.x + threadIdx.x;
    if (e >= E) return;
    int s = ei[e];
    int d = ei[E + e];
    float norm = g_dinv[s] * ew[e] * g_dinv[d];
    int pos = atomicAdd(&g_cnt[d], 1);
    g_edge[pos] = make_float2(__int_as_float(s), norm);
}

// ---------------- W1 transpose to bf16 ----------------
__global__ void k_wsplit(const float* __restrict__ W1) {
    int idx = blockIdx.x * blockDim.x + threadIdx.x;
    if (idx >= HID * IN_FEAT) return;
    int k = idx & (IN_FEAT - 1);
    int n = idx >> 9;
    g_WT[n * IN_FEAT + k] = __float2bfloat16(W1[k * HID + n]);
}

// ---------------- GEMM1: h1 = x @ W1 via single-pass bf16 WMMA ----------------
#define A_TILE_ELEMS (TM * KPAD)            // 4608
#define B_TILE_ELEMS (HID * KPAD)           // 9216
#define BUF_ELEMS (A_TILE_ELEMS + B_TILE_ELEMS)   // 13824
#define G1_SMEM (2 * BUF_ELEMS * 2)         // 55296 B
#define EPI_STRIDE 132                      // fp32 staging stride (floats)
#define G1_T 128

__device__ __forceinline__ uint32_t smem_u32(const void* p) {
    uint32_t a;
    asm("{ .reg .u64 t; cvta.to.shared.u64 t, %1; cvt.u32.u64 %0, t; }" : "=r"(a) : "l"(p));
    return a;
}
__device__ __forceinline__ void cp16(uint32_t dst, const void* src) {
    asm volatile("cp.async.ca.shared.global [%0], [%1], 16;" :: "r"(dst), "l"(src));
}
__device__ __forceinline__ uint32_t pk2h(float a, float b) {
    __half2 h = __floats2half2_rn(a, b);
    return *(uint32_t*)&h;
}

__global__ void __launch_bounds__(G1_T, 3) k_gemm1_wmma(const float* __restrict__ A, int M) {
    extern __shared__ __align__(16) __nv_bfloat16 sm[];
    const int t = threadIdx.x;
    const int wid = t >> 5;
    const int wm = wid & 1;        // rows wm*32
    const int wn = wid >> 1;       // cols wn*64
    const int rowBase = blockIdx.x * TM;
    const uint32_t sb = smem_u32(sm);

    wmma::fragment<wmma::accumulator, 16, 16, 16, float> acc[2][4];
#pragma unroll
    for (int i = 0; i < 2; i++)
#pragma unroll
        for (int j = 0; j < 4; j++) wmma::fill_fragment(acc[i][j], 0.0f);

    float4 avreg[8];

    auto loadA = [&](int c) {
#pragma unroll
        for (int l = 0; l < 8; l++) {
            int idx = t + l * G1_T;
            int r = idx >> 4;
            int g = idx & 15;
            float4 v = make_float4(0.f, 0.f, 0.f, 0.f);
            if (rowBase + r < M)
                v = *(const float4*)(A + (size_t)(rowBase + r) * IN_FEAT + c * BK + g * 4);
            avreg[l] = v;
        }
    };

    auto cpB = [&](int c, int buf) {
        uint32_t bh = sb + (uint32_t)(buf * BUF_ELEMS + A_TILE_ELEMS) * 2;
#pragma unroll
        for (int l = 0; l < 8; l++) {
            int idx = t + l * G1_T;
            int n = idx >> 3;
            int g = idx & 7;
            uint32_t so = (uint32_t)(n * KPAD + g * 8) * 2;
            cp16(bh + so, g_WT + (size_t)n * IN_FEAT + c * BK + g * 8);
        }
        asm volatile("cp.async.commit_group;" ::: "memory");
    };

    auto storeA = [&](int buf) {
        __nv_bfloat16* Ah = sm + (size_t)buf * BUF_ELEMS;
#pragma unroll
        for (int l = 0; l < 8; l++) {
            int idx = t + l * G1_T;
            int r = idx >> 4;
            int g = idx & 15;
            float4 v = avreg[l];
            int off = r * KPAD + g * 4;
            *(__nv_bfloat162*)(Ah + off)     = __nv_bfloat162(__float2bfloat16(v.x), __float2bfloat16(v.y));
            *(__nv_bfloat162*)(Ah + off + 2) = __nv_bfloat162(__float2bfloat16(v.z), __float2bfloat16(v.w));
        }
    };

    auto compute = [&](int buf) {
        const __nv_bfloat16* Ah = sm + (size_t)buf * BUF_ELEMS;
        const __nv_bfloat16* Bh = Ah + A_TILE_ELEMS;
#pragma unroll
        for (int kk = 0; kk < BK; kk += 16) {
            wmma::fragment<wmma::matrix_a, 16, 16, 16, __nv_bfloat16, wmma::row_major> fa[2];
            wmma::fragment<wmma::matrix_b, 16, 16, 16, __nv_bfloat16, wmma::col_major> fb[4];
#pragma unroll
            for (int i = 0; i < 2; i++)
                wmma::load_matrix_sync(fa[i], Ah + (wm * 32 + i * 16) * KPAD + kk, KPAD);
#pragma unroll
            for (int j = 0; j < 4; j++)
                wmma::load_matrix_sync(fb[j], Bh + (wn * 64 + j * 16) * KPAD + kk, KPAD);
#pragma unroll
            for (int i = 0; i < 2; i++)
#pragma unroll
                for (int j = 0; j < 4; j++)
                    wmma::mma_sync(acc[i][j], fa[i], fb[j], acc[i][j]);
        }
    };

    loadA(0);
    cpB(0, 0);
    storeA(0);
    asm volatile("cp.async.wait_group 0;" ::: "memory");
    __syncthreads();

    const int NSTAGE = IN_FEAT / BK;  // 8
    for (int c = 0; c < NSTAGE; c++) {
        const int cur = c & 1;
        const int nxt = 1 - cur;
        if (c + 1 < NSTAGE) {
            loadA(c + 1);
            cpB(c + 1, nxt);
        }
        compute(cur);
        if (c + 1 < NSTAGE) {
            storeA(nxt);
            asm volatile("cp.async.wait_group 0;" ::: "memory");
        }
        __syncthreads();
    }

    // epilogue: stage fp32 accs in smem, convert to fp16, coalesced STG
    {
        float* fs = (float*)sm;
#pragma unroll
        for (int i = 0; i < 2; i++)
#pragma unroll
            for (int j = 0; j < 4; j++)
                wmma::store_matrix_sync(fs + (wm * 32 + i * 16) * EPI_STRIDE + wn * 64 + j * 16,
                                        acc[i][j], EPI_STRIDE, wmma::mem_row_major);
        __syncthreads();
#pragma unroll
        for (int u = 0; u < 8; u++) {
            int idx = t + u * G1_T;
            int r = idx >> 4;
            int c = (idx & 15) * 8;
            const float* src = fs + r * EPI_STRIDE + c;
            uint4 o;
            o.x = pk2h(src[0], src[1]);
            o.y = pk2h(src[2], src[3]);
            o.z = pk2h(src[4], src[5]);
            o.w = pk2h(src[6], src[7]);
            *(uint4*)(g_h1h + (size_t)(rowBase + r) * HID + c) = o;
        }
    }
}

// ---------------- layer1 aggregate + ELU + @W2 (warp per node, smem W2) ----------------
__device__ __forceinline__ float4 h4f(uint2 u) {
    __half2 a = *(__half2*)&u.x;
    __half2 b = *(__half2*)&u.y;
    float2 fa = __half22float2(a);
    float2 fb = __half22float2(b);
    return make_float4(fa.x, fa.y, fb.x, fb.y);
}

__global__ void __launch_bounds__(256) k_agg1_fused(const float* __restrict__ b1,
                                                    const float* __restrict__ W2, int n) {
    __shared__ __align__(16) float sW2[HID * NC];   // 896 floats = 3.5 KB
    for (int i = threadIdx.x; i < HID * NC; i += 256)
        sW2[i] = W2[i];
    __syncthreads();

    int node = (int)(((size_t)blockIdx.x * blockDim.x + threadIdx.x) >> 5);
    int lane = threadIdx.x & 31;
    if (node >= n) return;

    const int beg = g_rowptr[node];
    const int end = g_rowptr[node + 1];
    float d = g_dinv[node];
    float dd = d * d;

    // self-loop init (fp16 h1)
    float4 acc = h4f(*((const uint2*)(g_h1h + (size_t)node * HID) + lane));
    acc.x *= dd; acc.y *= dd; acc.z *= dd; acc.w *= dd;

    int e = beg;
    for (; e + 4 <= end; e += 4) {
        float2 e0 = g_edge[e];
        float2 e1 = g_edge[e + 1];
        float2 e2 = g_edge[e + 2];
        float2 e3 = g_edge[e + 3];
        uint2 u0 = *((const uint2*)(g_h1h + (size_t)__float_as_int(e0.x) * HID) + lane);
        uint2 u1 = *((const uint2*)(g_h1h + (size_t)__float_as_int(e1.x) * HID) + lane);
        uint2 u2 = *((const uint2*)(g_h1h + (size_t)__float_as_int(e2.x) * HID) + lane);
        uint2 u3 = *((const uint2*)(g_h1h + (size_t)__float_as_int(e3.x) * HID) + lane);
        float4 v0 = h4f(u0), v1 = h4f(u1), v2 = h4f(u2), v3 = h4f(u3);
        acc.x = fmaf(v0.x, e0.y, acc.x); acc.y = fmaf(v0.y, e0.y, acc.y);
        acc.z = fmaf(v0.z, e0.y, acc.z); acc.w = fmaf(v0.w, e0.y, acc.w);
        acc.x = fmaf(v1.x, e1.y, acc.x); acc.y = fmaf(v1.y, e1.y, acc.y);
        acc.z = fmaf(v1.z, e1.y, acc.z); acc.w = fmaf(v1.w, e1.y, acc.w);
        acc.x = fmaf(v2.x, e2.y, acc.x); acc.y = fmaf(v2.y, e2.y, acc.y);
        acc.z = fmaf(v2.z, e2.y, acc.z); acc.w = fmaf(v2.w, e2.y, acc.w);
        acc.x = fmaf(v3.x, e3.y, acc.x); acc.y = fmaf(v3.y, e3.y, acc.y);
        acc.z = fmaf(v3.z, e3.y, acc.z); acc.w = fmaf(v3.w, e3.y, acc.w);
    }
    for (; e < end; e++) {
        float2 ed = g_edge[e];
        float4 v = h4f(*((const uint2*)(g_h1h + (size_t)__float_as_int(ed.x) * HID) + lane));
        acc.x = fmaf(v.x, ed.y, acc.x);
        acc.y = fmaf(v.y, ed.y, acc.y);
        acc.z = fmaf(v.z, ed.y, acc.z);
        acc.w = fmaf(v.w, ed.y, acc.w);
    }

    // epilogue: +b1 (one float4), ELU, @W2 from smem (7x LDS.128 per thread)
    float4 bv = *(const float4*)(b1 + lane * 4);
    float av[4] = {acc.x + bv.x, acc.y + bv.y, acc.z + bv.z, acc.w + bv.w};
#pragma unroll
    for (int j = 0; j < 4; j++)
        av[j] = av[j] > 0.0f ? av[j] : expm1f(av[j]);

    float w[28];
    const float4* wrow = (const float4*)(sW2 + lane * 28);   // 112B, 16B-aligned
#pragma unroll
    for (int k = 0; k < 7; k++)
        *(float4*)&w[k * 4] = wrow[k];

    float sv[NC];
#pragma unroll
    for (int c = 0; c < NC; c++) sv[c] = 0.0f;
#pragma unroll
    for (int j = 0; j < 4; j++)
#pragma unroll
        for (int c = 0; c < NC; c++)
            sv[c] = fmaf(av[j], w[j * 7 + c], sv[c]);

#pragma unroll
    for (int off = 16; off > 0; off >>= 1)
#pragma unroll
        for (int c = 0; c < NC; c++) sv[c] += __shfl_down_sync(0xffffffffu, sv[c], off);
    if (lane == 0) {
        uint4 o;
        o.x = pk2h(sv[0], sv[1]);
        o.y = pk2h(sv[2], sv[3]);
        o.z = pk2h(sv[4], sv[5]);
        o.w = pk2h(sv[6], 0.0f);
        *(uint4*)(g_h2h + (size_t)node * 8) = o;
    }
}

// ---------------- layer2 aggregate (fp16 h2) + bias + log_softmax (8 lanes per node) ----------------
__global__ void __launch_bounds__(256) k_agg2_fused(const float* __restrict__ b2,
                                                    float* __restrict__ out, int n) {
    int node = (int)(((size_t)blockIdx.x * blockDim.x + threadIdx.x) >> 3);
    int l8 = threadIdx.x & 7;
    if (node >= n) return;
    const unsigned gmask = 0xFFu << (threadIdx.x & 24);

    const int beg = g_rowptr[node];
    const int end = g_rowptr[node + 1];
    float d = g_dinv[node];
    float acc = __half2float(g_h2h[(size_t)node * 8 + l8]) * d * d;

    int e = beg;
    for (; e + 4 <= end; e += 4) {
        float2 e0 = g_edge[e];
        float2 e1 = g_edge[e + 1];
        float2 e2 = g_edge[e + 2];
        float2 e3 = g_edge[e + 3];
        float v0 = __half2float(g_h2h[(size_t)__float_as_int(e0.x) * 8 + l8]);
        float v1 = __half2float(g_h2h[(size_t)__float_as_int(e1.x) * 8 + l8]);
        float v2 = __half2float(g_h2h[(size_t)__float_as_int(e2.x) * 8 + l8]);
        float v3 = __half2float(g_h2h[(size_t)__float_as_int(e3.x) * 8 + l8]);
        acc = fmaf(v0, e0.y, acc);
        acc = fmaf(v1, e1.y, acc);
        acc = fmaf(v2, e2.y, acc);
        acc = fmaf(v3, e3.y, acc);
    }
    for (; e < end; e++) {
        float2 ed = g_edge[e];
        acc = fmaf(__half2float(g_h2h[(size_t)__float_as_int(ed.x) * 8 + l8]), ed.y, acc);
    }

    float z = (l8 < NC) ? acc + b2[l8] : -1e30f;
    float m = z;
#pragma unroll
    for (int off = 4; off > 0; off >>= 1)
        m = fmaxf(m, __shfl_xor_sync(gmask, m, off));
    float ex = (l8 < NC) ? expf(z - m) : 0.0f;
    float sum = ex;
#pragma unroll
    for (int off = 4; off > 0; off >>= 1)
        sum += __shfl_xor_sync(gmask, sum, off);
    float lse = m + logf(sum);
    if (l8 < NC) out[(size_t)node * NC + l8] = z - lse;
}

// ---------------- launcher ----------------
extern "C" void kernel_launch(void* const* d_in, const int* in_sizes, int n_in,
                              void* d_out, int out_size) {
    const float* x  = (const float*)d_in[0];
    const int*   ei = (const int*)d_in[1];
    const float* ew = (const float*)d_in[2];
    const float* W1 = (const float*)d_in[3];
    const float* b1 = (const float*)d_in[4];
    const float* W2 = (const float*)d_in[5];
    const float* b2 = (const float*)d_in[6];
    float* out = (float*)d_out;

    const int Nn = in_sizes[0] / IN_FEAT;   // 100000
    const int E  = in_sizes[2];             // 1600000
    const int nb = (Nn + SCAN_B - 1) / SCAN_B;

    static cudaStream_t s1 = 0;
    static cudaEvent_t ev_fork = 0, ev_join = 0;
    static int init_done = 0;
    if (!init_done) {
        cudaFuncSetAttribute(k_gemm1_wmma, cudaFuncAttributeMaxDynamicSharedMemorySize, G1_SMEM);
        cudaStreamCreateWithFlags(&s1, cudaStreamNonBlocking);
        cudaEventCreateWithFlags(&ev_fork, cudaEventDisableTiming);
        cudaEventCreateWithFlags(&ev_join, cudaEventDisableTiming);
        init_done = 1;
    }

    // fork: edge/CSR chain on s1, GEMM chain on the origin stream
    cudaEventRecord(ev_fork, 0);
    cudaStreamWaitEvent(s1, ev_fork, 0);

    k_wsplit<<<(HID * IN_FEAT + 255) / 256, 256>>>(W1);
    k_deg_init<<<(Nn + 255) / 256, 256, 0, s1>>>(Nn);
    k_deg_acc<<<(E + 255) / 256, 256, 0, s1>>>(ei, ew, E);

    k_gemm1_wmma<<<(Nn + TM - 1) / TM, G1_T, G1_SMEM>>>(x, Nn);   // 4th launch (ncu slot)

    k_scan1<<<nb, SCAN_B, 0, s1>>>(Nn);   // dinv fused
    k_scan2<<<1, 256, 0, s1>>>(nb, Nn);
    k_scan3<<<nb, SCAN_B, 0, s1>>>(Nn);
    k_reorder<<<(E + 255) / 256, 256, 0, s1>>>(ei, ew, E);

    // join: aggregation needs both GEMM output and CSR
    cudaEventRecord(ev_join, s1);
    cudaStreamWaitEvent(0, ev_join, 0);

    k_agg1_fused<<<(Nn + 7) / 8, 256>>>(b1, W2, Nn);    // warp per node, smem W2
    k_agg2_fused<<<(Nn + 31) / 32, 256>>>(b2, out, Nn); // 8 lanes per node
}